// round 16
// baseline (speedup 1.0000x reference)
#include <cuda_runtime.h>
#include <stdint.h>

#define NSEG 6
#define NC   512
#define NP   16384   // 128*128
#define BINS 16

// ---------------- scratch (__device__ globals, no allocation) ----------------
__device__ uint32_t g_mbits[NSEG * 512];       // mask bits (for k_bins)
__device__ float    g_maskf[NSEG * NP];        // mask as fp32 0/1 (pool stream)
__device__ int      g_pb  [NSEG * BINS];       // bin position interval begin (incl)
__device__ int      g_pe  [NSEG * BINS];       // bin position interval end   (incl)
__device__ float    g_inv [NSEG * BINS];       // 1/denom per (seg,bin)
__device__ float    g_ys  [NSEG * NC * BINS];  // pooled features
__device__ float    g_wA  [NSEG * 2048];
__device__ float    g_wB  [NSEG * 512];

__global__ void k_nop() {}

// ---------------- n-th set bit (n < popc(m)) ---------------------------------
__device__ __forceinline__ int nth_set_bit32(unsigned m, int n) {
    for (int i = 0; i < n; i++) m &= m - 1;    // clear n lowest set bits
    return __ffs(m) - 1;
}

// ---------------- kernel 1a: mask words + fp32 mask, full-chip ---------------
__global__ void k_mask(const int* __restrict__ parsing) {
    const int seg = blockIdx.y;
    const int p   = blockIdx.x * 1024 + threadIdx.x;
    const int h = p >> 7, w = p & 127;
    // nearest resize 256->128: src = (2h, 2w)
    const int v = parsing[seg * 65536 + h * 512 + w * 2];
    g_maskf[seg * NP + p] = (v != 0) ? 1.0f : 0.0f;
    unsigned word = __ballot_sync(0xffffffffu, v != 0);
    if ((threadIdx.x & 31) == 0)
        g_mbits[seg * 512 + (p >> 5)] = word;
}

// ---------------- kernel 1b: scan words + bin intervals ----------------------
__global__ void k_bins() {
    const int seg = blockIdx.x;
    const int tid = threadIdx.x;              // 0..511
    const int lane = tid & 31, wid = tid >> 5; // 16 warps

    const unsigned word = g_mbits[seg * 512 + tid];
    const int cnt = __popc(word);

    __shared__ int warp_tot[16];
    __shared__ int warp_off[16];
    __shared__ int sL;
    __shared__ int s_pb[BINS], s_pe[BINS];
    __shared__ int s_t0[BINS], s_t1[BINS];

    int x = cnt;
    #pragma unroll
    for (int off = 1; off < 32; off <<= 1) {
        int y = __shfl_up_sync(0xffffffffu, x, off);
        if (lane >= off) x += y;
    }
    if (lane == 31) warp_tot[wid] = x;
    if (tid < BINS) { s_pb[tid] = NP; s_pe[tid] = -1; }
    __syncthreads();
    if (tid < 16) {
        int s = 0;
        for (int i = 0; i < tid; i++) s += warp_tot[i];
        warp_off[tid] = s;
        if (tid == 15) sL = s + warp_tot[15];
    }
    __syncthreads();
    const int excl = warp_off[wid] + x - cnt;
    const int L = sL;

    if (tid < BINS) {
        int k = tid;
        int start = (k * L) / BINS;
        int end   = ((k + 1) * L + BINS - 1) / BINS;
        int denom = max(end - start, 1);
        g_inv[seg * BINS + k] = 1.0f / (float)denom;
        s_t0[k] = start;
        s_t1[k] = end - 1;
    }
    __syncthreads();

    if (cnt > 0) {
        const int lo = excl, hi = excl + cnt;
        const int base_p = tid * 32;
        #pragma unroll
        for (int k = 0; k < BINS; k++) {
            int t0 = s_t0[k];
            if (t0 >= lo && t0 < hi) s_pb[k] = base_p + nth_set_bit32(word, t0 - lo);
            int t1 = s_t1[k];
            if (t1 >= lo && t1 < hi) s_pe[k] = base_p + nth_set_bit32(word, t1 - lo);
        }
    }
    __syncthreads();

    if (tid < BINS) {
        g_pb[seg * BINS + tid] = s_pb[tid];
        g_pe[seg * BINS + tid] = s_pe[tid];
    }
}

// ---------------- kernel 2: warp-per-(channel,bin-pair), predicated edges ----
// grid (NC, NSEG), 256 threads = 8 warps. Warp w owns bins {w, w+8}: iterate
// the inclusive float4 word range of the interval; zero out-of-interval
// elements via compare+select (only first/last word can fail). No divergent
// edge lanes, no atomics.
__global__ void __launch_bounds__(256, 6) k_pool(const float* __restrict__ xs) {
    const int seg = blockIdx.y;
    const int c   = blockIdx.x;
    const int tid = threadIdx.x, lane = tid & 31, w = tid >> 5;  // w: 0..7
    __shared__ int   spb[BINS], spe[BINS];
    __shared__ float sinv[BINS];
    if (tid < BINS) {
        spb [tid] = g_pb [seg * BINS + tid];
        spe [tid] = g_pe [seg * BINS + tid];
        sinv[tid] = g_inv[seg * BINS + tid];
    }
    __syncthreads();

    const float4* __restrict__ x4 = (const float4*)(xs + ((size_t)seg * NC + c) * NP);
    const float4* __restrict__ m4 = (const float4*)(g_maskf + (size_t)seg * NP);
    float* __restrict__ yo = g_ys + ((size_t)seg * NC + c) * BINS;

    #pragma unroll
    for (int kk = 0; kk < 2; kk++) {
        const int k = w + kk * 8;
        const int b = spb[k], e = spe[k];
        float acc = 0.0f;
        const int t0 = b >> 2, t1 = e >> 2;          // inclusive word range
        #pragma unroll 4
        for (int t = t0 + lane; t <= t1; t += 32) {  // empty when b>e (t0>t1+..)
            float4 v = x4[t];
            float4 m = m4[t];
            const int p = t << 2;
            float f0 = (p     >= b && p     <= e) ? m.x : 0.0f;
            float f1 = (p + 1 >= b && p + 1 <= e) ? m.y : 0.0f;
            float f2 = (p + 2 >= b && p + 2 <= e) ? m.z : 0.0f;
            float f3 = (p + 3 >= b && p + 3 <= e) ? m.w : 0.0f;
            acc += v.x * f0 + v.y * f1 + v.z * f2 + v.w * f3;
        }
        #pragma unroll
        for (int off = 16; off; off >>= 1) acc += __shfl_down_sync(0xffffffffu, acc, off);
        if (lane == 0) yo[k] = acc * sinv[k];
    }
}

// ---------------- fcA: block-per-row, full load batch up front ---------------
__global__ void k_fcA(const float* __restrict__ W, const float* __restrict__ b) {
    const int row = blockIdx.x;                 // 0..12287
    const int seg = row >> 11;
    const int tid = threadIdx.x;
    const int lane = tid & 31, wid = tid >> 5;

    const float4* __restrict__ W4 = (const float4*)(W + (size_t)row * 8192);
    const float4* __restrict__ x4 = (const float4*)(g_ys + (size_t)seg * 8192);

    float4 w0 = W4[0 * 256 + tid];
    float4 w1 = W4[1 * 256 + tid];
    float4 w2 = W4[2 * 256 + tid];
    float4 w3 = W4[3 * 256 + tid];
    float4 w4 = W4[4 * 256 + tid];
    float4 w5 = W4[5 * 256 + tid];
    float4 w6 = W4[6 * 256 + tid];
    float4 w7 = W4[7 * 256 + tid];

    float acc0 = 0.f, acc1 = 0.f;
    {
        float4 v;
        v = x4[0 * 256 + tid]; acc0 += w0.x*v.x + w0.y*v.y + w0.z*v.z + w0.w*v.w;
        v = x4[1 * 256 + tid]; acc1 += w1.x*v.x + w1.y*v.y + w1.z*v.z + w1.w*v.w;
        v = x4[2 * 256 + tid]; acc0 += w2.x*v.x + w2.y*v.y + w2.z*v.z + w2.w*v.w;
        v = x4[3 * 256 + tid]; acc1 += w3.x*v.x + w3.y*v.y + w3.z*v.z + w3.w*v.w;
        v = x4[4 * 256 + tid]; acc0 += w4.x*v.x + w4.y*v.y + w4.z*v.z + w4.w*v.w;
        v = x4[5 * 256 + tid]; acc1 += w5.x*v.x + w5.y*v.y + w5.z*v.z + w5.w*v.w;
        v = x4[6 * 256 + tid]; acc0 += w6.x*v.x + w6.y*v.y + w6.z*v.z + w6.w*v.w;
        v = x4[7 * 256 + tid]; acc1 += w7.x*v.x + w7.y*v.y + w7.z*v.z + w7.w*v.w;
    }
    float acc = acc0 + acc1;
    #pragma unroll
    for (int off = 16; off; off >>= 1) acc += __shfl_down_sync(0xffffffffu, acc, off);

    __shared__ float ssum[8];
    if (lane == 0) ssum[wid] = acc;
    __syncthreads();
    if (tid == 0) {
        float s = ssum[0] + ssum[1] + ssum[2] + ssum[3]
                + ssum[4] + ssum[5] + ssum[6] + ssum[7];
        g_wA[row] = s + b[row];
    }
}

// ---------------- fcB: 4 rows/block, fcA-style batched loads -----------------
__global__ void k_fcB(const float* __restrict__ W, const float* __restrict__ b) {
    const int tid = threadIdx.x;
    const int lane = tid & 31, wid = tid >> 5;   // 8 warps
    const int u     = tid & 63;                  // 0..63 within row
    const int row   = blockIdx.x * 4 + (tid >> 6);  // 0..3071
    const int seg   = row >> 9;

    const float4* __restrict__ W4 = (const float4*)(W + (size_t)row * 2048);
    const float4* __restrict__ x4 = (const float4*)(g_wA + (size_t)seg * 2048);

    float4 w0 = W4[0 * 64 + u];
    float4 w1 = W4[1 * 64 + u];
    float4 w2 = W4[2 * 64 + u];
    float4 w3 = W4[3 * 64 + u];
    float4 w4 = W4[4 * 64 + u];
    float4 w5 = W4[5 * 64 + u];
    float4 w6 = W4[6 * 64 + u];
    float4 w7 = W4[7 * 64 + u];

    float acc0 = 0.f, acc1 = 0.f;
    {
        float4 v;
        v = x4[0 * 64 + u]; acc0 += w0.x*v.x + w0.y*v.y + w0.z*v.z + w0.w*v.w;
        v = x4[1 * 64 + u]; acc1 += w1.x*v.x + w1.y*v.y + w1.z*v.z + w1.w*v.w;
        v = x4[2 * 64 + u]; acc0 += w2.x*v.x + w2.y*v.y + w2.z*v.z + w2.w*v.w;
        v = x4[3 * 64 + u]; acc1 += w3.x*v.x + w3.y*v.y + w3.z*v.z + w3.w*v.w;
        v = x4[4 * 64 + u]; acc0 += w4.x*v.x + w4.y*v.y + w4.z*v.z + w4.w*v.w;
        v = x4[5 * 64 + u]; acc1 += w5.x*v.x + w5.y*v.y + w5.z*v.z + w5.w*v.w;
        v = x4[6 * 64 + u]; acc0 += w6.x*v.x + w6.y*v.y + w6.z*v.z + w6.w*v.w;
        v = x4[7 * 64 + u]; acc1 += w7.x*v.x + w7.y*v.y + w7.z*v.z + w7.w*v.w;
    }
    float acc = acc0 + acc1;
    #pragma unroll
    for (int off = 16; off; off >>= 1) acc += __shfl_down_sync(0xffffffffu, acc, off);

    __shared__ float ssum[8];
    if (lane == 0) ssum[wid] = acc;               // 2 warps per row
    __syncthreads();
    if (tid < 4)
        g_wB[blockIdx.x * 4 + tid] = ssum[2 * tid] + ssum[2 * tid + 1]
                                   + b[blockIdx.x * 4 + tid];
}

// ---------------- generic GEMV (warp per row), per-seg weights ---------------
template <int NDIM>
__global__ void k_gemv(const float* __restrict__ W, const float* __restrict__ xin,
                       const float* __restrict__ b, float* __restrict__ y,
                       int rows_per_seg, int x_seg_stride, int y_seg_stride) {
    const int gwarp = (blockIdx.x * blockDim.x + threadIdx.x) >> 5;
    const int lane  = threadIdx.x & 31;
    const int row   = gwarp;
    const int seg   = row / rows_per_seg;
    const int m     = row - seg * rows_per_seg;

    const float4* W4 = (const float4*)(W + (size_t)row * NDIM);
    const float4* x4 = (const float4*)(xin + (size_t)seg * x_seg_stride);

    float acc = 0.0f;
    #pragma unroll 4
    for (int i = lane; i < NDIM / 4; i += 32) {
        float4 w = W4[i];
        float4 v = x4[i];
        acc += w.x * v.x + w.y * v.y + w.z * v.z + w.w * v.w;
    }
    #pragma unroll
    for (int off = 16; off; off >>= 1) acc += __shfl_down_sync(0xffffffffu, acc, off);
    if (lane == 0) y[(size_t)seg * y_seg_stride + m] = acc + b[row];
}

// ---------------- GEMV with SHARED weights (p1/p2/p3 cascade stages) ---------
template <int NDIM, int ROWS_PER_SEG>
__global__ void k_gemv_sh(const float* __restrict__ W, const float* __restrict__ b,
                          float* __restrict__ out, int xoff, int yoff) {
    const int gwarp = (blockIdx.x * blockDim.x + threadIdx.x) >> 5;
    const int lane  = threadIdx.x & 31;
    const int seg   = gwarp / ROWS_PER_SEG;
    const int m     = gwarp - seg * ROWS_PER_SEG;

    const float4* W4 = (const float4*)(W + (size_t)m * NDIM);
    const float4* x4 = (const float4*)(out + seg * 960 + xoff);

    float acc = 0.0f;
    #pragma unroll
    for (int i = lane; i < NDIM / 4; i += 32) {
        float4 w = W4[i];
        float4 v = x4[i];
        acc += w.x * v.x + w.y * v.y + w.z * v.z + w.w * v.w;
    }
    #pragma unroll
    for (int off = 16; off; off >>= 1) acc += __shfl_down_sync(0xffffffffu, acc, off);
    if (lane == 0) out[seg * 960 + yoff + m] = acc + b[m];
}

// ---------------- launch ------------------------------------------------------
extern "C" void kernel_launch(void* const* d_in, const int* in_sizes, int n_in,
                              void* d_out, int out_size) {
    const float* xs      = (const float*)d_in[0];
    const int*   parsing = (const int*)  d_in[1];
    const float* fcA_w   = (const float*)d_in[2];
    const float* fcA_b   = (const float*)d_in[3];
    const float* fcB_w   = (const float*)d_in[4];
    const float* fcB_b   = (const float*)d_in[5];
    const float* fcC_w   = (const float*)d_in[6];
    const float* fcC_b   = (const float*)d_in[7];
    const float* p1_w    = (const float*)d_in[8];
    const float* p1_b    = (const float*)d_in[9];
    const float* p2_w    = (const float*)d_in[10];
    const float* p2_b    = (const float*)d_in[11];
    const float* p3_w    = (const float*)d_in[12];
    const float* p3_b    = (const float*)d_in[13];
    float* out = (float*)d_out;                     // [6,1,960]

    float* wBp; cudaGetSymbolAddress((void**)&wBp, g_wB);

    // 1) nop — keep k_pool in the ncu capture slot (4th launch)
    k_nop<<<1, 32>>>();

    // 2) mask words + fp32 mask, full-chip
    k_mask<<<dim3(16, NSEG), 1024>>>(parsing);

    // 3) word scan + bin intervals
    k_bins<<<NSEG, 512>>>();

    // 4) interval pooling (201 MB): 8 warps/channel, 2 bins/warp, predicated
    k_pool<<<dim3(NC, NSEG), 256>>>(xs);

    // 5) fcA: block-per-row (402 MB)
    k_fcA<<<NSEG * 2048, 256>>>(fcA_w, fcA_b);

    // 6) fcB: 4 rows/block, batched loads (25 MB)
    k_fcB<<<NSEG * 512 / 4, 256>>>(fcB_w, fcB_b);

    // 7) fcC: 6x[512x512] -> out[seg*960 + 0..511] (w0)
    k_gemv<512><<<(NSEG * 512) / 8, 256>>>(fcC_w, wBp, fcC_b, out, 512, 512, 960);

    // 8-10) p1/p2/p3 cascade, shared weights, full-width grids
    k_gemv_sh<512, 256><<<(NSEG * 256) / 8, 256>>>(p1_w, p1_b, out, 0,   512);
    k_gemv_sh<256, 128><<<(NSEG * 128) / 8, 256>>>(p2_w, p2_b, out, 512, 768);
    k_gemv_sh<128,  64><<<(NSEG *  64) / 8, 256>>>(p3_w, p3_b, out, 768, 896);
}

// round 17
// speedup vs baseline: 1.0138x; 1.0138x over previous
#include <cuda_runtime.h>
#include <stdint.h>

#define NSEG 6
#define NC   512
#define NP   16384   // 128*128
#define BINS 16

// ---------------- scratch (__device__ globals, no allocation) ----------------
__device__ uint32_t g_mbits[NSEG * 512];       // mask bits (for k_bins)
__device__ float    g_maskf[NSEG * NP];        // mask as fp32 0/1 (pool stream)
__device__ int      g_pb  [NSEG * BINS];       // bin position interval begin (incl)
__device__ int      g_pe  [NSEG * BINS];       // bin position interval end   (incl)
__device__ float    g_inv [NSEG * BINS];       // 1/denom per (seg,bin)
__device__ float    g_ys  [NSEG * NC * BINS];  // pooled features
__device__ float    g_wA  [NSEG * 2048];
__device__ float    g_wB  [NSEG * 512];

__global__ void k_nop() {}

// ---------------- n-th set bit (n < popc(m)) ---------------------------------
__device__ __forceinline__ int nth_set_bit32(unsigned m, int n) {
    for (int i = 0; i < n; i++) m &= m - 1;    // clear n lowest set bits
    return __ffs(m) - 1;
}

// ---------------- kernel 1a: mask words + fp32 mask, full-chip ---------------
__global__ void k_mask(const int* __restrict__ parsing) {
    const int seg = blockIdx.y;
    const int p   = blockIdx.x * 1024 + threadIdx.x;
    const int h = p >> 7, w = p & 127;
    // nearest resize 256->128: src = (2h, 2w)
    const int v = parsing[seg * 65536 + h * 512 + w * 2];
    g_maskf[seg * NP + p] = (v != 0) ? 1.0f : 0.0f;
    unsigned word = __ballot_sync(0xffffffffu, v != 0);
    if ((threadIdx.x & 31) == 0)
        g_mbits[seg * 512 + (p >> 5)] = word;
}

// ---------------- kernel 1b: scan words + bin intervals ----------------------
__global__ void k_bins() {
    const int seg = blockIdx.x;
    const int tid = threadIdx.x;              // 0..511
    const int lane = tid & 31, wid = tid >> 5; // 16 warps

    const unsigned word = g_mbits[seg * 512 + tid];
    const int cnt = __popc(word);

    __shared__ int warp_tot[16];
    __shared__ int warp_off[16];
    __shared__ int sL;
    __shared__ int s_pb[BINS], s_pe[BINS];
    __shared__ int s_t0[BINS], s_t1[BINS];

    int x = cnt;
    #pragma unroll
    for (int off = 1; off < 32; off <<= 1) {
        int y = __shfl_up_sync(0xffffffffu, x, off);
        if (lane >= off) x += y;
    }
    if (lane == 31) warp_tot[wid] = x;
    if (tid < BINS) { s_pb[tid] = NP; s_pe[tid] = -1; }
    __syncthreads();
    if (tid < 16) {
        int s = 0;
        for (int i = 0; i < tid; i++) s += warp_tot[i];
        warp_off[tid] = s;
        if (tid == 15) sL = s + warp_tot[15];
    }
    __syncthreads();
    const int excl = warp_off[wid] + x - cnt;
    const int L = sL;

    if (tid < BINS) {
        int k = tid;
        int start = (k * L) / BINS;
        int end   = ((k + 1) * L + BINS - 1) / BINS;
        int denom = max(end - start, 1);
        g_inv[seg * BINS + k] = 1.0f / (float)denom;
        s_t0[k] = start;
        s_t1[k] = end - 1;
    }
    __syncthreads();

    if (cnt > 0) {
        const int lo = excl, hi = excl + cnt;
        const int base_p = tid * 32;
        #pragma unroll
        for (int k = 0; k < BINS; k++) {
            int t0 = s_t0[k];
            if (t0 >= lo && t0 < hi) s_pb[k] = base_p + nth_set_bit32(word, t0 - lo);
            int t1 = s_t1[k];
            if (t1 >= lo && t1 < hi) s_pe[k] = base_p + nth_set_bit32(word, t1 - lo);
        }
    }
    __syncthreads();

    if (tid < BINS) {
        g_pb[seg * BINS + tid] = s_pb[tid];
        g_pe[seg * BINS + tid] = s_pe[tid];
    }
}

// ---------------- kernel 2: warp-per-(channel,bin-pair), edge-word predication
// grid (NC, NSEG), 256 threads = 8 warps. Warp w owns bins {w, w+8}. The only
// partial float4 words of a bin interval are the FIRST (t0) and LAST (t1):
// lanes 0/1 handle those with per-element selects; interior words [t0+1,t1-1]
// are plain 2xLDG.128 + 4 FFMA with zero predicate cost. No atomics.
__global__ void __launch_bounds__(256, 6) k_pool(const float* __restrict__ xs) {
    const int seg = blockIdx.y;
    const int c   = blockIdx.x;
    const int tid = threadIdx.x, lane = tid & 31, w = tid >> 5;  // w: 0..7
    __shared__ int   spb[BINS], spe[BINS];
    __shared__ float sinv[BINS];
    if (tid < BINS) {
        spb [tid] = g_pb [seg * BINS + tid];
        spe [tid] = g_pe [seg * BINS + tid];
        sinv[tid] = g_inv[seg * BINS + tid];
    }
    __syncthreads();

    const float4* __restrict__ x4 = (const float4*)(xs + ((size_t)seg * NC + c) * NP);
    const float4* __restrict__ m4 = (const float4*)(g_maskf + (size_t)seg * NP);
    float* __restrict__ yo = g_ys + ((size_t)seg * NC + c) * BINS;

    #pragma unroll
    for (int kk = 0; kk < 2; kk++) {
        const int k = w + kk * 8;
        const int b = spb[k], e = spe[k];
        float acc = 0.0f;
        if (b <= e) {
            const int t0 = b >> 2, t1 = e >> 2;      // inclusive word range
            // edge words: lane 0 -> t0, lane 1 -> t1 (skip if same word)
            if (lane == 0 || (lane == 1 && t1 > t0)) {
                const int t = (lane == 0) ? t0 : t1;
                float4 v = x4[t];
                float4 m = m4[t];
                const int p = t << 2;
                float f0 = (p     >= b && p     <= e) ? m.x : 0.0f;
                float f1 = (p + 1 >= b && p + 1 <= e) ? m.y : 0.0f;
                float f2 = (p + 2 >= b && p + 2 <= e) ? m.z : 0.0f;
                float f3 = (p + 3 >= b && p + 3 <= e) ? m.w : 0.0f;
                acc += v.x * f0 + v.y * f1 + v.z * f2 + v.w * f3;
            }
            // interior words, branch-free
            #pragma unroll 4
            for (int t = t0 + 1 + lane; t <= t1 - 1; t += 32) {
                float4 v = x4[t];
                float4 m = m4[t];
                acc += v.x * m.x + v.y * m.y + v.z * m.z + v.w * m.w;
            }
        }
        #pragma unroll
        for (int off = 16; off; off >>= 1) acc += __shfl_down_sync(0xffffffffu, acc, off);
        if (lane == 0) yo[k] = acc * sinv[k];
    }
}

// ---------------- fcA: block-per-row, full load batch up front ---------------
__global__ void k_fcA(const float* __restrict__ W, const float* __restrict__ b) {
    const int row = blockIdx.x;                 // 0..12287
    const int seg = row >> 11;
    const int tid = threadIdx.x;
    const int lane = tid & 31, wid = tid >> 5;

    const float4* __restrict__ W4 = (const float4*)(W + (size_t)row * 8192);
    const float4* __restrict__ x4 = (const float4*)(g_ys + (size_t)seg * 8192);

    float4 w0 = W4[0 * 256 + tid];
    float4 w1 = W4[1 * 256 + tid];
    float4 w2 = W4[2 * 256 + tid];
    float4 w3 = W4[3 * 256 + tid];
    float4 w4 = W4[4 * 256 + tid];
    float4 w5 = W4[5 * 256 + tid];
    float4 w6 = W4[6 * 256 + tid];
    float4 w7 = W4[7 * 256 + tid];

    float acc0 = 0.f, acc1 = 0.f;
    {
        float4 v;
        v = x4[0 * 256 + tid]; acc0 += w0.x*v.x + w0.y*v.y + w0.z*v.z + w0.w*v.w;
        v = x4[1 * 256 + tid]; acc1 += w1.x*v.x + w1.y*v.y + w1.z*v.z + w1.w*v.w;
        v = x4[2 * 256 + tid]; acc0 += w2.x*v.x + w2.y*v.y + w2.z*v.z + w2.w*v.w;
        v = x4[3 * 256 + tid]; acc1 += w3.x*v.x + w3.y*v.y + w3.z*v.z + w3.w*v.w;
        v = x4[4 * 256 + tid]; acc0 += w4.x*v.x + w4.y*v.y + w4.z*v.z + w4.w*v.w;
        v = x4[5 * 256 + tid]; acc1 += w5.x*v.x + w5.y*v.y + w5.z*v.z + w5.w*v.w;
        v = x4[6 * 256 + tid]; acc0 += w6.x*v.x + w6.y*v.y + w6.z*v.z + w6.w*v.w;
        v = x4[7 * 256 + tid]; acc1 += w7.x*v.x + w7.y*v.y + w7.z*v.z + w7.w*v.w;
    }
    float acc = acc0 + acc1;
    #pragma unroll
    for (int off = 16; off; off >>= 1) acc += __shfl_down_sync(0xffffffffu, acc, off);

    __shared__ float ssum[8];
    if (lane == 0) ssum[wid] = acc;
    __syncthreads();
    if (tid == 0) {
        float s = ssum[0] + ssum[1] + ssum[2] + ssum[3]
                + ssum[4] + ssum[5] + ssum[6] + ssum[7];
        g_wA[row] = s + b[row];
    }
}

// ---------------- fcB: 4 rows/block, fcA-style batched loads -----------------
__global__ void k_fcB(const float* __restrict__ W, const float* __restrict__ b) {
    const int tid = threadIdx.x;
    const int lane = tid & 31, wid = tid >> 5;   // 8 warps
    const int u     = tid & 63;                  // 0..63 within row
    const int row   = blockIdx.x * 4 + (tid >> 6);  // 0..3071
    const int seg   = row >> 9;

    const float4* __restrict__ W4 = (const float4*)(W + (size_t)row * 2048);
    const float4* __restrict__ x4 = (const float4*)(g_wA + (size_t)seg * 2048);

    float4 w0 = W4[0 * 64 + u];
    float4 w1 = W4[1 * 64 + u];
    float4 w2 = W4[2 * 64 + u];
    float4 w3 = W4[3 * 64 + u];
    float4 w4 = W4[4 * 64 + u];
    float4 w5 = W4[5 * 64 + u];
    float4 w6 = W4[6 * 64 + u];
    float4 w7 = W4[7 * 64 + u];

    float acc0 = 0.f, acc1 = 0.f;
    {
        float4 v;
        v = x4[0 * 64 + u]; acc0 += w0.x*v.x + w0.y*v.y + w0.z*v.z + w0.w*v.w;
        v = x4[1 * 64 + u]; acc1 += w1.x*v.x + w1.y*v.y + w1.z*v.z + w1.w*v.w;
        v = x4[2 * 64 + u]; acc0 += w2.x*v.x + w2.y*v.y + w2.z*v.z + w2.w*v.w;
        v = x4[3 * 64 + u]; acc1 += w3.x*v.x + w3.y*v.y + w3.z*v.z + w3.w*v.w;
        v = x4[4 * 64 + u]; acc0 += w4.x*v.x + w4.y*v.y + w4.z*v.z + w4.w*v.w;
        v = x4[5 * 64 + u]; acc1 += w5.x*v.x + w5.y*v.y + w5.z*v.z + w5.w*v.w;
        v = x4[6 * 64 + u]; acc0 += w6.x*v.x + w6.y*v.y + w6.z*v.z + w6.w*v.w;
        v = x4[7 * 64 + u]; acc1 += w7.x*v.x + w7.y*v.y + w7.z*v.z + w7.w*v.w;
    }
    float acc = acc0 + acc1;
    #pragma unroll
    for (int off = 16; off; off >>= 1) acc += __shfl_down_sync(0xffffffffu, acc, off);

    __shared__ float ssum[8];
    if (lane == 0) ssum[wid] = acc;               // 2 warps per row
    __syncthreads();
    if (tid < 4)
        g_wB[blockIdx.x * 4 + tid] = ssum[2 * tid] + ssum[2 * tid + 1]
                                   + b[blockIdx.x * 4 + tid];
}

// ---------------- generic GEMV (warp per row), per-seg weights ---------------
template <int NDIM>
__global__ void k_gemv(const float* __restrict__ W, const float* __restrict__ xin,
                       const float* __restrict__ b, float* __restrict__ y,
                       int rows_per_seg, int x_seg_stride, int y_seg_stride) {
    const int gwarp = (blockIdx.x * blockDim.x + threadIdx.x) >> 5;
    const int lane  = threadIdx.x & 31;
    const int row   = gwarp;
    const int seg   = row / rows_per_seg;
    const int m     = row - seg * rows_per_seg;

    const float4* W4 = (const float4*)(W + (size_t)row * NDIM);
    const float4* x4 = (const float4*)(xin + (size_t)seg * x_seg_stride);

    float acc = 0.0f;
    #pragma unroll 4
    for (int i = lane; i < NDIM / 4; i += 32) {
        float4 w = W4[i];
        float4 v = x4[i];
        acc += w.x * v.x + w.y * v.y + w.z * v.z + w.w * v.w;
    }
    #pragma unroll
    for (int off = 16; off; off >>= 1) acc += __shfl_down_sync(0xffffffffu, acc, off);
    if (lane == 0) y[(size_t)seg * y_seg_stride + m] = acc + b[row];
}

// ---------------- GEMV with SHARED weights (p1/p2/p3 cascade stages) ---------
template <int NDIM, int ROWS_PER_SEG>
__global__ void k_gemv_sh(const float* __restrict__ W, const float* __restrict__ b,
                          float* __restrict__ out, int xoff, int yoff) {
    const int gwarp = (blockIdx.x * blockDim.x + threadIdx.x) >> 5;
    const int lane  = threadIdx.x & 31;
    const int seg   = gwarp / ROWS_PER_SEG;
    const int m     = gwarp - seg * ROWS_PER_SEG;

    const float4* W4 = (const float4*)(W + (size_t)m * NDIM);
    const float4* x4 = (const float4*)(out + seg * 960 + xoff);

    float acc = 0.0f;
    #pragma unroll
    for (int i = lane; i < NDIM / 4; i += 32) {
        float4 w = W4[i];
        float4 v = x4[i];
        acc += w.x * v.x + w.y * v.y + w.z * v.z + w.w * v.w;
    }
    #pragma unroll
    for (int off = 16; off; off >>= 1) acc += __shfl_down_sync(0xffffffffu, acc, off);
    if (lane == 0) out[seg * 960 + yoff + m] = acc + b[m];
}

// ---------------- launch ------------------------------------------------------
extern "C" void kernel_launch(void* const* d_in, const int* in_sizes, int n_in,
                              void* d_out, int out_size) {
    const float* xs      = (const float*)d_in[0];
    const int*   parsing = (const int*)  d_in[1];
    const float* fcA_w   = (const float*)d_in[2];
    const float* fcA_b   = (const float*)d_in[3];
    const float* fcB_w   = (const float*)d_in[4];
    const float* fcB_b   = (const float*)d_in[5];
    const float* fcC_w   = (const float*)d_in[6];
    const float* fcC_b   = (const float*)d_in[7];
    const float* p1_w    = (const float*)d_in[8];
    const float* p1_b    = (const float*)d_in[9];
    const float* p2_w    = (const float*)d_in[10];
    const float* p2_b    = (const float*)d_in[11];
    const float* p3_w    = (const float*)d_in[12];
    const float* p3_b    = (const float*)d_in[13];
    float* out = (float*)d_out;                     // [6,1,960]

    float* wBp; cudaGetSymbolAddress((void**)&wBp, g_wB);

    // 1) nop — keep k_pool in the ncu capture slot (4th launch)
    k_nop<<<1, 32>>>();

    // 2) mask words + fp32 mask, full-chip
    k_mask<<<dim3(16, NSEG), 1024>>>(parsing);

    // 3) word scan + bin intervals
    k_bins<<<NSEG, 512>>>();

    // 4) interval pooling (201 MB): 8 warps/channel, 2 bins/warp, edge-word pred
    k_pool<<<dim3(NC, NSEG), 256>>>(xs);

    // 5) fcA: block-per-row (402 MB)
    k_fcA<<<NSEG * 2048, 256>>>(fcA_w, fcA_b);

    // 6) fcB: 4 rows/block, batched loads (25 MB)
    k_fcB<<<NSEG * 512 / 4, 256>>>(fcB_w, fcB_b);

    // 7) fcC: 6x[512x512] -> out[seg*960 + 0..511] (w0)
    k_gemv<512><<<(NSEG * 512) / 8, 256>>>(fcC_w, wBp, fcC_b, out, 512, 512, 960);

    // 8-10) p1/p2/p3 cascade, shared weights, full-width grids
    k_gemv_sh<512, 256><<<(NSEG * 256) / 8, 256>>>(p1_w, p1_b, out, 0,   512);
    k_gemv_sh<256, 128><<<(NSEG * 128) / 8, 256>>>(p2_w, p2_b, out, 512, 768);
    k_gemv_sh<128,  64><<<(NSEG *  64) / 8, 256>>>(p3_w, p3_b, out, 768, 896);
}